// round 14
// baseline (speedup 1.0000x reference)
#include <cuda_runtime.h>

// ---------------- scratch (device globals; no allocation allowed) ----------------
#define NB 64
__device__ float g_buf1[NB*16*128*128]; // enc conv1 out (pre-BN)
__device__ float g_buf2[NB*16*64*64];   // enc conv2 out
__device__ float g_buf3[NB*32*32*32];   // enc conv3 out (q_in pre-BN)
__device__ float g_buf4[NB*32*32*32];   // q_out
__device__ float g_buf5[NB*16*64*64];   // dec convT1 out
__device__ float g_buf6[NB*16*128*128]; // dec convT2 out
__device__ float g_buf7[NB*256*256];    // dec convT3 out (pre-BN)
__device__ float g_sum[6*32];
__device__ float g_sq[6*32];
__device__ float g_cnorm[512];
__device__ float g_loss[2];   // [0]=quant SSE, [1]=recon SSE

typedef unsigned long long ull;

__device__ __forceinline__ float warp_red(float v) {
    #pragma unroll
    for (int o = 16; o; o >>= 1) v += __shfl_down_sync(0xffffffffu, v, o);
    return v;
}

// ---------------- packed f32x2 helpers ----------------
__device__ __forceinline__ ull pk2(float lo, float hi) {
    ull r; asm("mov.b64 %0, {%1, %2};" : "=l"(r) : "f"(lo), "f"(hi)); return r;
}
__device__ __forceinline__ void upk2(ull v, float& lo, float& hi) {
    asm("mov.b64 {%0, %1}, %2;" : "=f"(lo), "=f"(hi) : "l"(v));
}
__device__ __forceinline__ ull fma2(ull a, ull b, ull c) {
    ull d; asm("fma.rn.f32x2 %0, %1, %2, %3;" : "=l"(d) : "l"(a), "l"(b), "l"(c)); return d;
}

// ---------------- tiny helpers (split so conv2 lands in the profiled launch slot #4) ------
__global__ void zero_k() {
    int i = threadIdx.x;
    if (i < 192) { g_sum[i] = 0.f; g_sq[i] = 0.f; }
    if (i < 2) g_loss[i] = 0.f;
}

__global__ void cnorm_k(const float* __restrict__ cb) {
    int k = blockIdx.x * 256 + threadIdx.x;
    if (k < 512) {
        float s = 0.f;
        #pragma unroll
        for (int c = 0; c < 32; c++) { float v = cb[k*32 + c]; s = fmaf(v, v, s); }
        g_cnorm[k] = s;
    }
}

// per-block BN finalize into shared
template<int C>
__device__ __forceinline__ void bn_block(const float* __restrict__ gsum_in,
                                         const float* __restrict__ gsq_in,
                                         const float* __restrict__ gam,
                                         const float* __restrict__ bet,
                                         float cnt, float* ssc, float* ssh, int tid) {
    if (tid < C) {
        float m = gsum_in[tid] / cnt;
        float var = gsq_in[tid] / cnt - m * m;
        float s = gam[tid] * rsqrtf(var + 1e-5f);
        ssc[tid] = s;
        ssh[tid] = bet[tid] - m * s;
    }
}

// ---------------- strided conv (k=4,s=2,p=1), smem-staged input tile (round-8 exact) ------
template<int CIN, int COUT, int HO, int WO, int PY, int PX, bool PRE>
__global__ void conv_s2_k(const float* __restrict__ in, const float* __restrict__ w,
                          const float* __restrict__ bias,
                          const float* __restrict__ gsum_in, const float* __restrict__ gsq_in,
                          const float* __restrict__ gam, const float* __restrict__ bet, float cnt,
                          float* __restrict__ out,
                          float* __restrict__ gsum, float* __restrict__ gsq) {
    constexpr int HI = HO * 2, WI = WO * 2;
    constexpr int TBX = 16, TBY = 8;
    constexpr int HT = TBY * PY, WT = TBX * PX;   // output tile per block
    constexpr int CX = WO / WT;
    constexpr int TROWS = 2 * HT + 2, TCOLS = 2 * WT + 2;
    constexpr int TCS = TCOLS + 1;
    constexpr int NPIX = PY * PX;
    static_assert(COUT % 4 == 0, "packed path");
    __shared__ float ws[CIN * 16 * COUT];   // [ic][ky*4+kx][oc]
    __shared__ float tile[TROWS * TCS];
    __shared__ float ssum[COUT], ssq[COUT];
    __shared__ float ssc[(PRE ? CIN : 1)], ssh[(PRE ? CIN : 1)];
    int tid = threadIdx.x;
    for (int i = tid; i < CIN * 16 * COUT; i += 128) {
        int oc = i % COUT; int r = i / COUT; int k = r & 15; int ic = r >> 4;
        ws[i] = w[(oc * CIN + ic) * 16 + k];
    }
    if (tid < COUT) { ssum[tid] = 0.f; ssq[tid] = 0.f; }
    if constexpr (PRE) bn_block<CIN>(gsum_in, gsq_in, gam, bet, cnt, ssc, ssh, tid);

    int b = blockIdx.y;
    int chX = blockIdx.x % CX, chY = blockIdx.x / CX;
    int gy0 = 2 * (chY * HT) - 1, gx0 = 2 * (chX * WT) - 1;
    int tx = tid % TBX, ty = tid / TBX;
    int OYl = ty * PY, OXl = tx * PX;
    int OY = chY * HT + OYl, OX = chX * WT + OXl;

    ull acc2[NPIX][COUT / 2];
    #pragma unroll
    for (int p = 0; p < NPIX; p++)
        #pragma unroll
        for (int j = 0; j < COUT / 2; j++) acc2[p][j] = 0ull;

    const float* inb = in + (size_t)b * CIN * HI * WI;
    #pragma unroll 1
    for (int ic = 0; ic < CIN; ic++) {
        const float* ip = inb + (size_t)ic * HI * WI;
        __syncthreads();   // previous-iter readers done; orders ws/ssc on iter 0
        float sc = 1.f, sh = 0.f;
        if constexpr (PRE) { sc = ssc[ic]; sh = ssh[ic]; }
        for (int idx = tid; idx < TROWS * TCOLS; idx += 128) {
            int r = idx / TCOLS, c = idx % TCOLS;
            int gy = gy0 + r, gx = gx0 + c;
            float v = 0.f;
            if ((unsigned)gy < (unsigned)HI && (unsigned)gx < (unsigned)WI) {
                v = ip[(size_t)gy * WI + gx];
                if constexpr (PRE) v = fmaxf(fmaf(v, sc, sh), 0.f);
            }
            tile[r * TCS + c] = v;
        }
        __syncthreads();
        #pragma unroll
        for (int ky = 0; ky < 4; ky++) {
            #pragma unroll
            for (int kx = 0; kx < 4; kx++) {
                const ulonglong2* w4 = (const ulonglong2*)&ws[(ic * 16 + ky * 4 + kx) * COUT];
                ull w2[COUT / 2];
                #pragma unroll
                for (int jj = 0; jj < COUT / 4; jj++) {
                    ulonglong2 ww = w4[jj];
                    w2[2 * jj] = ww.x; w2[2 * jj + 1] = ww.y;
                }
                #pragma unroll
                for (int dy = 0; dy < PY; dy++) {
                    #pragma unroll
                    for (int dx = 0; dx < PX; dx++) {
                        float v = tile[(2 * (OYl + dy) + ky) * TCS + 2 * (OXl + dx) + kx];
                        ull v2 = pk2(v, v);
                        int pi = dy * PX + dx;
                        #pragma unroll
                        for (int j = 0; j < COUT / 2; j++)
                            acc2[pi][j] = fma2(v2, w2[j], acc2[pi][j]);
                    }
                }
            }
        }
    }

    float acc[NPIX][COUT];
    #pragma unroll
    for (int p = 0; p < NPIX; p++)
        #pragma unroll
        for (int j = 0; j < COUT / 2; j++) upk2(acc2[p][j], acc[p][2*j], acc[p][2*j+1]);

    float* ob = out + ((size_t)b * COUT) * HO * WO;
    #pragma unroll
    for (int oc = 0; oc < COUT; oc++) {
        float bz = bias[oc];
        #pragma unroll
        for (int dy = 0; dy < PY; dy++) {
            #pragma unroll
            for (int dx = 0; dx < PX; dx++) {
                int pi = dy * PX + dx;
                float v = acc[pi][oc] + bz;
                acc[pi][oc] = v;
                ob[(size_t)oc * HO * WO + (size_t)(OY + dy) * WO + OX + dx] = v;
            }
        }
    }

    int lane = tid & 31;
    #pragma unroll
    for (int oc = 0; oc < COUT; oc++) {
        float s = 0.f, qs = 0.f;
        #pragma unroll
        for (int p = 0; p < NPIX; p++) { float v = acc[p][oc]; s += v; qs = fmaf(v, v, qs); }
        s = warp_red(s); qs = warp_red(qs);
        if (lane == 0) { atomicAdd(&ssum[oc], s); atomicAdd(&ssq[oc], qs); }
    }
    __syncthreads();
    if (tid < COUT) { atomicAdd(&gsum[tid], ssum[tid]); atomicAdd(&gsq[tid], ssq[tid]); }
}

// ---------------- transposed conv via parity decomposition (round-8 exact, COUT%4==0) ------
template<int CIN, int COUT, int HO, int WO, int PP, bool PRE>
__global__ void convT_k(const float* __restrict__ in, const float* __restrict__ w,
                        const float* __restrict__ bias,
                        const float* __restrict__ gsum_in, const float* __restrict__ gsq_in,
                        const float* __restrict__ gam, const float* __restrict__ bet, float cnt,
                        float* __restrict__ out,
                        float* __restrict__ gsum, float* __restrict__ gsq) {
    constexpr int HI = HO / 2, WI = WO / 2;
    constexpr int WW = WO / 2;
    constexpr int TBX = 16, TBY = 8;
    constexpr int CX = WW / (TBX * PP);
    constexpr int NPIX = PP * PP;
    constexpr int PS = PP + 1;
    __shared__ float ws[CIN * 16 * COUT];   // [ic][ky*4+kx][oc]
    __shared__ float ssum[COUT], ssq[COUT];
    __shared__ float ssc[(PRE ? CIN : 1)], ssh[(PRE ? CIN : 1)];
    int tid = threadIdx.x;
    for (int i = tid; i < CIN * 16 * COUT; i += 128) {
        int oc = i % COUT; int r = i / COUT; int k = r & 15; int ic = r >> 4;
        ws[i] = w[(ic * COUT + oc) * 16 + k];   // torch layout [in][out][kh][kw]
    }
    if (tid < COUT) { ssum[tid] = 0.f; ssq[tid] = 0.f; }
    if constexpr (PRE) bn_block<CIN>(gsum_in, gsq_in, gam, bet, cnt, ssc, ssh, tid);
    __syncthreads();

    int b = blockIdx.y;
    int cz = blockIdx.z; int cy = cz >> 1, cx = cz & 1;
    int chX = blockIdx.x % CX, chY = blockIdx.x / CX;
    int tx = tid % TBX, ty = tid / TBX;
    int Y0 = (chY * TBY + ty) * PP, X0 = (chX * TBX + tx) * PP;

    ull acc2[NPIX][COUT / 2];
    #pragma unroll
    for (int p = 0; p < NPIX; p++)
        #pragma unroll
        for (int j = 0; j < COUT / 2; j++) acc2[p][j] = 0ull;

    const float* inb = in + (size_t)b * CIN * HI * WI;
    #pragma unroll 1
    for (int ic = 0; ic < CIN; ic++) {
        const float* ip = inb + (size_t)ic * HI * WI;
        float sc = 1.f, sh = 0.f;
        if constexpr (PRE) { sc = ssc[ic]; sh = ssh[ic]; }
        float p[PS][PS];
        #pragma unroll
        for (int r = 0; r < PS; r++) {
            int gy = Y0 + cy - 1 + r;
            bool yok = (unsigned)gy < (unsigned)HI;
            const float* rp = ip + (size_t)gy * WI;
            #pragma unroll
            for (int c = 0; c < PS; c++) {
                int gx = X0 + cx - 1 + c;
                float v = 0.f;
                if (yok && (unsigned)gx < (unsigned)WI) {
                    v = rp[gx];
                    if constexpr (PRE) v = fmaxf(fmaf(v, sc, sh), 0.f);
                }
                p[r][c] = v;
            }
        }
        #pragma unroll
        for (int t = 0; t < 2; t++) {
            #pragma unroll
            for (int s = 0; s < 2; s++) {
                int ky = (1 - cy) + 2 * t, kx = (1 - cx) + 2 * s;
                const float* wr = &ws[(ic * 16 + ky * 4 + kx) * COUT];
                const ulonglong2* w4 = (const ulonglong2*)wr;
                ull w2[COUT / 2];
                #pragma unroll
                for (int jj = 0; jj < COUT / 4; jj++) {
                    ulonglong2 ww = w4[jj];
                    w2[2 * jj] = ww.x; w2[2 * jj + 1] = ww.y;
                }
                #pragma unroll
                for (int dy = 0; dy < PP; dy++) {
                    #pragma unroll
                    for (int dx = 0; dx < PP; dx++) {
                        float v = p[dy + 1 - t][dx + 1 - s];
                        ull v2 = pk2(v, v);
                        int pi = dy * PP + dx;
                        #pragma unroll
                        for (int j = 0; j < COUT / 2; j++)
                            acc2[pi][j] = fma2(v2, w2[j], acc2[pi][j]);
                    }
                }
            }
        }
    }

    float acc[NPIX][COUT];
    #pragma unroll
    for (int p = 0; p < NPIX; p++)
        #pragma unroll
        for (int j = 0; j < COUT / 2; j++) upk2(acc2[p][j], acc[p][2*j], acc[p][2*j+1]);

    float* ob = out + ((size_t)b * COUT) * HO * WO;
    #pragma unroll
    for (int oc = 0; oc < COUT; oc++) {
        float bz = bias[oc];
        #pragma unroll
        for (int dy = 0; dy < PP; dy++) {
            #pragma unroll
            for (int dx = 0; dx < PP; dx++) {
                int pi = dy * PP + dx;
                float v = acc[pi][oc] + bz;
                acc[pi][oc] = v;
                int oy = 2 * (Y0 + dy) + cy, ox = 2 * (X0 + dx) + cx;
                ob[(size_t)oc * HO * WO + (size_t)oy * WO + ox] = v;
            }
        }
    }

    int lane = tid & 31;
    #pragma unroll
    for (int oc = 0; oc < COUT; oc++) {
        float s = 0.f, qs = 0.f;
        #pragma unroll
        for (int p = 0; p < NPIX; p++) { float v = acc[p][oc]; s += v; qs = fmaf(v, v, qs); }
        s = warp_red(s); qs = warp_red(qs);
        if (lane == 0) { atomicAdd(&ssum[oc], s); atomicAdd(&ssq[oc], qs); }
    }
    __syncthreads();
    if (tid < COUT) { atomicAdd(&gsum[tid], ssum[tid]); atomicAdd(&gsq[tid], ssq[tid]); }
}

// ---------------- convT3: COUT=1 with t-pair FFMA2 packing ----------------
// acc(dy,dx) packed as (t=0 partial, t=1 partial); fold lo+hi at the end.
template<int CIN, int HO, int WO, int PP, bool PRE>
__global__ void convT3_k(const float* __restrict__ in, const float* __restrict__ w,
                         const float* __restrict__ bias,
                         const float* __restrict__ gsum_in, const float* __restrict__ gsq_in,
                         const float* __restrict__ gam, const float* __restrict__ bet, float cnt,
                         float* __restrict__ out,
                         float* __restrict__ gsum, float* __restrict__ gsq) {
    constexpr int HI = HO / 2, WI = WO / 2;
    constexpr int TBX = 16, TBY = 8;
    constexpr int CX = WI / (TBX * PP);
    constexpr int NPIX = PP * PP;
    constexpr int PS = PP + 1;
    __shared__ float ws[CIN * 16];
    __shared__ float ssum1, ssq1;
    __shared__ float ssc[(PRE ? CIN : 1)], ssh[(PRE ? CIN : 1)];
    int tid = threadIdx.x;
    for (int i = tid; i < CIN * 16; i += 128) ws[i] = w[i];   // [in][1][kh][kw]
    if (tid == 0) { ssum1 = 0.f; ssq1 = 0.f; }
    if constexpr (PRE) bn_block<CIN>(gsum_in, gsq_in, gam, bet, cnt, ssc, ssh, tid);
    __syncthreads();

    int b = blockIdx.y;
    int cz = blockIdx.z; int cy = cz >> 1, cx = cz & 1;
    int chX = blockIdx.x % CX, chY = blockIdx.x / CX;
    int tx = tid % TBX, ty = tid / TBX;
    int Y0 = (chY * TBY + ty) * PP, X0 = (chX * TBX + tx) * PP;

    ull acc2[NPIX];
    #pragma unroll
    for (int p = 0; p < NPIX; p++) acc2[p] = 0ull;

    const float* inb = in + (size_t)b * CIN * HI * WI;
    int kyA = (1 - cy) * 4, kyB = (3 - cy) * 4;   // ky for t=0 / t=1, times 4
    int kx0 = 1 - cx, kx1 = 3 - cx;               // kx for s=0 / s=1
    #pragma unroll 1
    for (int ic = 0; ic < CIN; ic++) {
        const float* ip = inb + (size_t)ic * HI * WI;
        float sc = 1.f, sh = 0.f;
        if constexpr (PRE) { sc = ssc[ic]; sh = ssh[ic]; }
        float p[PS][PS];
        #pragma unroll
        for (int r = 0; r < PS; r++) {
            int gy = Y0 + cy - 1 + r;
            bool yok = (unsigned)gy < (unsigned)HI;
            const float* rp = ip + (size_t)gy * WI;
            #pragma unroll
            for (int c = 0; c < PS; c++) {
                int gx = X0 + cx - 1 + c;
                float v = 0.f;
                if (yok && (unsigned)gx < (unsigned)WI) {
                    v = rp[gx];
                    if constexpr (PRE) v = fmaxf(fmaf(v, sc, sh), 0.f);
                }
                p[r][c] = v;
            }
        }
        // packed weights: (w(t=0,s), w(t=1,s))
        const float* wi = &ws[ic * 16];
        ull wA = pk2(wi[kyA + kx0], wi[kyB + kx0]);   // s=0 -> col = dx+1
        ull wB = pk2(wi[kyA + kx1], wi[kyB + kx1]);   // s=1 -> col = dx
        // packed row pairs: pr[dy][c] = (p[dy+1][c], p[dy][c])
        ull pr[PP][PS];
        #pragma unroll
        for (int dy = 0; dy < PP; dy++)
            #pragma unroll
            for (int c = 0; c < PS; c++)
                pr[dy][c] = pk2(p[dy + 1][c], p[dy][c]);
        #pragma unroll
        for (int dy = 0; dy < PP; dy++) {
            #pragma unroll
            for (int dx = 0; dx < PP; dx++) {
                int pi = dy * PP + dx;
                acc2[pi] = fma2(pr[dy][dx + 1], wA, acc2[pi]);
                acc2[pi] = fma2(pr[dy][dx],     wB, acc2[pi]);
            }
        }
    }

    float acc[NPIX];
    float bz = bias[0];
    float s = 0.f, qs = 0.f;
    float* ob = out + (size_t)b * HO * WO;
    #pragma unroll
    for (int pi = 0; pi < NPIX; pi++) {
        float lo, hi;
        upk2(acc2[pi], lo, hi);
        float v = lo + hi + bz;
        acc[pi] = v;
        s += v; qs = fmaf(v, v, qs);
    }
    #pragma unroll
    for (int dy = 0; dy < PP; dy++) {
        #pragma unroll
        for (int dx = 0; dx < PP; dx++) {
            int oy = 2 * (Y0 + dy) + cy, ox = 2 * (X0 + dx) + cx;
            ob[(size_t)oy * WO + ox] = acc[dy * PP + dx];
        }
    }

    int lane = tid & 31;
    s = warp_red(s); qs = warp_red(qs);
    if (lane == 0) { atomicAdd(&ssum1, s); atomicAdd(&ssq1, qs); }
    __syncthreads();
    if (tid == 0) { atomicAdd(&gsum[0], ssum1); atomicAdd(&gsq[0], ssq1); }
}

// ---------------- quantizer: 2 adjacent vectors per thread (round-8 exact) ----------------
__global__ void quant_k(const float* __restrict__ q_raw, const float* __restrict__ cb,
                        float* __restrict__ qout, float* __restrict__ idx_out,
                        const float* __restrict__ gsum_in, const float* __restrict__ gsq_in,
                        const float* __restrict__ gam, const float* __restrict__ bet) {
    __shared__ float cbs[128 * 32];
    __shared__ float cns[128];
    __shared__ float ssc[32], ssh[32];
    int tid = threadIdx.x;   // 128 threads
    bn_block<32>(gsum_in, gsq_in, gam, bet, 65536.f, ssc, ssh, tid);
    __syncthreads();

    int vec = (blockIdx.x * 128 + tid) * 2;
    int b = vec >> 10, hw = vec & 1023;

    const float* base = q_raw + ((size_t)b * 32) * 1024 + hw;
    ull za[16], zb[16];
    #pragma unroll
    for (int j = 0; j < 16; j++) {
        float2 v0 = *(const float2*)(base + (size_t)(2*j)   * 1024);
        float2 v1 = *(const float2*)(base + (size_t)(2*j+1) * 1024);
        float a0 = fmaxf(fmaf(v0.x, ssc[2*j],   ssh[2*j]),   0.f);
        float b0 = fmaxf(fmaf(v0.y, ssc[2*j],   ssh[2*j]),   0.f);
        float a1 = fmaxf(fmaf(v1.x, ssc[2*j+1], ssh[2*j+1]), 0.f);
        float b1 = fmaxf(fmaf(v1.y, ssc[2*j+1], ssh[2*j+1]), 0.f);
        za[j] = pk2(a0, a1);
        zb[j] = pk2(b0, b1);
    }

    float bestA = 3.4e38f, bestB = 3.4e38f; int biA = 0, biB = 0;
    #pragma unroll 1
    for (int t = 0; t < 4; t++) {
        __syncthreads();
        const float4* src = (const float4*)(cb + (size_t)t * 128 * 32);
        float4* dst = (float4*)cbs;
        #pragma unroll
        for (int j = 0; j < 8; j++) dst[tid + 128 * j] = src[tid + 128 * j];
        cns[tid] = g_cnorm[t * 128 + tid];
        __syncthreads();
        #pragma unroll 1
        for (int k = 0; k < 128; k++) {
            const ulonglong2* cp = (const ulonglong2*)(cbs + k * 32);
            ull p0 = 0ull, p1 = 0ull, q0 = 0ull, q1 = 0ull;
            #pragma unroll
            for (int i = 0; i < 8; i++) {
                ulonglong2 c2 = cp[i];
                p0 = fma2(za[2*i],   c2.x, p0);
                p1 = fma2(za[2*i+1], c2.y, p1);
                q0 = fma2(zb[2*i],   c2.x, q0);
                q1 = fma2(zb[2*i+1], c2.y, q1);
            }
            float x0, x1, x2, x3, y0, y1, y2, y3;
            upk2(p0, x0, x1); upk2(p1, x2, x3);
            upk2(q0, y0, y1); upk2(q1, y2, y3);
            float cn = cns[k];
            float sA = cn - 2.f * ((x0 + x1) + (x2 + x3));
            float sB = cn - 2.f * ((y0 + y1) + (y2 + y3));
            if (sA < bestA) { bestA = sA; biA = t * 128 + k; }
            if (sB < bestB) { bestB = sB; biB = t * 128 + k; }
        }
    }

    idx_out[vec]     = (float)biA;
    idx_out[vec + 1] = (float)biB;
    float* qb = qout + ((size_t)b * 32) * 1024 + hw;
    const float4* ca = (const float4*)(cb + (size_t)biA * 32);
    const float4* cbp = (const float4*)(cb + (size_t)biB * 32);
    float sse = 0.f;
    #pragma unroll
    for (int j = 0; j < 8; j++) {
        float4 qa = __ldg(&ca[j]);
        float4 qv = __ldg(&cbp[j]);
        float a0, a1, a2, a3, b0, b1, b2, b3;
        upk2(za[2*j],   a0, a1);
        upk2(za[2*j+1], a2, a3);
        upk2(zb[2*j],   b0, b1);
        upk2(zb[2*j+1], b2, b3);
        *(float2*)(qb + (size_t)(4*j+0) * 1024) = make_float2(qa.x, qv.x);
        *(float2*)(qb + (size_t)(4*j+1) * 1024) = make_float2(qa.y, qv.y);
        *(float2*)(qb + (size_t)(4*j+2) * 1024) = make_float2(qa.z, qv.z);
        *(float2*)(qb + (size_t)(4*j+3) * 1024) = make_float2(qa.w, qv.w);
        float e;
        e = qa.x - a0; sse = fmaf(e, e, sse);
        e = qa.y - a1; sse = fmaf(e, e, sse);
        e = qa.z - a2; sse = fmaf(e, e, sse);
        e = qa.w - a3; sse = fmaf(e, e, sse);
        e = qv.x - b0; sse = fmaf(e, e, sse);
        e = qv.y - b1; sse = fmaf(e, e, sse);
        e = qv.z - b2; sse = fmaf(e, e, sse);
        e = qv.w - b3; sse = fmaf(e, e, sse);
    }
    sse = warp_red(sse);
    if ((tid & 31) == 0) atomicAdd(&g_loss[0], sse);
}

// ---------------- final: BN6-apply, 8 elems/thread via float4, recon SSE ----------------
// grid MUST be 4194304 / (256*8) = 2048 blocks.
__global__ void final_k(const float* __restrict__ x, float* __restrict__ dout,
                        const float* __restrict__ gsum_in, const float* __restrict__ gsq_in,
                        const float* __restrict__ gam, const float* __restrict__ bet) {
    __shared__ float wsum[8];
    __shared__ float sbn[2];
    if (threadIdx.x == 0) {
        float m = gsum_in[0] * (1.f / 4194304.f);
        float var = gsq_in[0] * (1.f / 4194304.f) - m * m;
        float s = gam[0] * rsqrtf(var + 1e-5f);
        sbn[0] = s; sbn[1] = bet[0] - m * s;
    }
    __syncthreads();
    float sc = sbn[0], sh = sbn[1];
    size_t i0 = ((size_t)blockIdx.x * 256 + threadIdx.x) * 8;
    float s = 0.f;
    #pragma unroll
    for (int h = 0; h < 2; h++) {
        float4 v = *(const float4*)(g_buf7 + i0 + 4 * h);
        float4 xv = *(const float4*)(x + i0 + 4 * h);
        float y0 = fmaf(v.x, sc, sh), y1 = fmaf(v.y, sc, sh);
        float y2 = fmaf(v.z, sc, sh), y3 = fmaf(v.w, sc, sh);
        *(float4*)(dout + i0 + 4 * h) = make_float4(y0, y1, y2, y3);
        float d0 = xv.x - y0, d1 = xv.y - y1, d2 = xv.z - y2, d3 = xv.w - y3;
        s = fmaf(d0, d0, fmaf(d1, d1, fmaf(d2, d2, fmaf(d3, d3, s))));
    }
    s = warp_red(s);
    if ((threadIdx.x & 31) == 0) wsum[threadIdx.x >> 5] = s;
    __syncthreads();
    if (threadIdx.x == 0) {
        float t = 0.f;
        #pragma unroll
        for (int j = 0; j < 8; j++) t += wsum[j];
        atomicAdd(&g_loss[1], t);
    }
}

__global__ void loss_k(float* __restrict__ dloss) {
    dloss[0] = 1.2f * g_loss[0] * (1.f / 2097152.f) + g_loss[1] * (1.f / 4194304.f);
}

// ---------------- launcher ----------------
extern "C" void kernel_launch(void* const* d_in, const int* in_sizes, int n_in,
                              void* d_out, int out_size) {
    const float* x      = (const float*)d_in[0];
    const float* enc_w1 = (const float*)d_in[1];
    const float* enc_b1 = (const float*)d_in[2];
    const float* enc_w2 = (const float*)d_in[3];
    const float* enc_b2 = (const float*)d_in[4];
    const float* enc_w3 = (const float*)d_in[5];
    const float* enc_b3 = (const float*)d_in[6];
    const float* enc_g1 = (const float*)d_in[7];
    const float* enc_be1= (const float*)d_in[8];
    const float* enc_g2 = (const float*)d_in[9];
    const float* enc_be2= (const float*)d_in[10];
    const float* enc_g3 = (const float*)d_in[11];
    const float* enc_be3= (const float*)d_in[12];
    const float* cb     = (const float*)d_in[13];
    const float* dec_w1 = (const float*)d_in[14];
    const float* dec_b1 = (const float*)d_in[15];
    const float* dec_w2 = (const float*)d_in[16];
    const float* dec_b2 = (const float*)d_in[17];
    const float* dec_w3 = (const float*)d_in[18];
    const float* dec_b3 = (const float*)d_in[19];
    const float* dec_g1 = (const float*)d_in[20];
    const float* dec_be1= (const float*)d_in[21];
    const float* dec_g2 = (const float*)d_in[22];
    const float* dec_be2= (const float*)d_in[23];
    const float* dec_g3 = (const float*)d_in[24];
    const float* dec_be3= (const float*)d_in[25];

    float* o = (float*)d_out;
    float* o_loss = o + 4194304;
    float* o_idx  = o + 4194305;

    static float *buf1,*buf2,*buf3,*buf4,*buf5,*buf6,*buf7,*sum,*sq;
    static bool init = false;
    if (!init) {
        cudaGetSymbolAddress((void**)&buf1, g_buf1);
        cudaGetSymbolAddress((void**)&buf2, g_buf2);
        cudaGetSymbolAddress((void**)&buf3, g_buf3);
        cudaGetSymbolAddress((void**)&buf4, g_buf4);
        cudaGetSymbolAddress((void**)&buf5, g_buf5);
        cudaGetSymbolAddress((void**)&buf6, g_buf6);
        cudaGetSymbolAddress((void**)&buf7, g_buf7);
        cudaGetSymbolAddress((void**)&sum,  g_sum);
        cudaGetSymbolAddress((void**)&sq,   g_sq);
        init = true;
    }

    zero_k<<<1, 256>>>();                                              // launch 1
    cnorm_k<<<2, 256>>>(cb);                                           // launch 2

    // encoder (round-13 exact)
    conv_s2_k<1,16,128,128,2,2,false><<<dim3(32, NB), 128>>>(          // launch 3
        x, enc_w1, enc_b1, nullptr, nullptr, nullptr, nullptr, 0.f,
        buf1, sum + 0, sq + 0);
    conv_s2_k<16,16,64,64,2,2,true><<<dim3(8, NB), 128>>>(             // launch 4 (profiled)
        buf1, enc_w2, enc_b2, sum + 0, sq + 0, enc_g1, enc_be1, 1048576.f,
        buf2, sum + 32, sq + 32);
    conv_s2_k<16,32,32,32,1,2,true><<<dim3(4, NB), 128>>>(             // launch 5
        buf2, enc_w3, enc_b3, sum + 32, sq + 32, enc_g2, enc_be2, 262144.f,
        buf3, sum + 64, sq + 64);

    // quantizer (round-13 exact)
    quant_k<<<256, 128>>>(buf3, cb, buf4, o_idx, sum + 64, sq + 64, enc_g3, enc_be3);  // launch 6

    // decoder
    convT_k<32,16,64,64,2,false><<<dim3(2, NB, 4), 128>>>(             // launch 7
        buf4, dec_w1, dec_b1, nullptr, nullptr, nullptr, nullptr, 0.f,
        buf5, sum + 96, sq + 96);
    convT_k<16,16,128,128,2,true><<<dim3(8, NB, 4), 128>>>(            // launch 8
        buf5, dec_w2, dec_b2, sum + 96, sq + 96, dec_g1, dec_be1, 262144.f,
        buf6, sum + 128, sq + 128);
    convT3_k<16,256,256,4,true><<<dim3(8, NB, 4), 128>>>(              // launch 9
        buf6, dec_w3, dec_b3, sum + 128, sq + 128, dec_g2, dec_be2, 1048576.f,
        buf7, sum + 160, sq + 160);

    // output + losses  (2048 blocks x 256 thr x 8 elems = 4194304)
    final_k<<<2048, 256>>>(x, o, sum + 160, sq + 160, dec_g3, dec_be3);  // launch 10
    loss_k<<<1, 1>>>(o_loss);                                             // launch 11
}

// round 15
// speedup vs baseline: 1.0331x; 1.0331x over previous
#include <cuda_runtime.h>

// ---------------- scratch (device globals; no allocation allowed) ----------------
#define NB 64
__device__ float g_buf1[NB*16*128*128]; // enc conv1 out (pre-BN)
__device__ float g_buf2[NB*16*64*64];   // enc conv2 out
__device__ float g_buf3[NB*32*32*32];   // enc conv3 out (q_in pre-BN)
__device__ float g_buf4[NB*32*32*32];   // q_out
__device__ float g_buf5[NB*16*64*64];   // dec convT1 out
__device__ float g_buf6[NB*16*128*128]; // dec convT2 out
__device__ float g_buf7[NB*256*256];    // dec convT3 out (pre-BN)
__device__ float g_sum[6*32];
__device__ float g_sq[6*32];
__device__ float g_cnorm[512];
__device__ float g_loss[2];   // [0]=quant SSE, [1]=recon SSE

typedef unsigned long long ull;

__device__ __forceinline__ float warp_red(float v) {
    #pragma unroll
    for (int o = 16; o; o >>= 1) v += __shfl_down_sync(0xffffffffu, v, o);
    return v;
}

// ---------------- packed f32x2 helpers ----------------
__device__ __forceinline__ ull pk2(float lo, float hi) {
    ull r; asm("mov.b64 %0, {%1, %2};" : "=l"(r) : "f"(lo), "f"(hi)); return r;
}
__device__ __forceinline__ void upk2(ull v, float& lo, float& hi) {
    asm("mov.b64 {%0, %1}, %2;" : "=f"(lo), "=f"(hi) : "l"(v));
}
__device__ __forceinline__ ull fma2(ull a, ull b, ull c) {
    ull d; asm("fma.rn.f32x2 %0, %1, %2, %3;" : "=l"(d) : "l"(a), "l"(b), "l"(c)); return d;
}

// ---------------- init: zero accumulators + codebook norms (merged, one launch) ----------
__global__ void init_k(const float* __restrict__ cb) {
    int i = blockIdx.x * 256 + threadIdx.x;   // grid 2 x 256 -> 512
    if (i < 192) { g_sum[i] = 0.f; g_sq[i] = 0.f; }
    if (i < 2) g_loss[i] = 0.f;
    if (i < 512) {
        float s = 0.f;
        #pragma unroll
        for (int c = 0; c < 32; c++) { float v = cb[i*32 + c]; s = fmaf(v, v, s); }
        g_cnorm[i] = s;
    }
}

// per-block BN finalize into shared
template<int C>
__device__ __forceinline__ void bn_block(const float* __restrict__ gsum_in,
                                         const float* __restrict__ gsq_in,
                                         const float* __restrict__ gam,
                                         const float* __restrict__ bet,
                                         float cnt, float* ssc, float* ssh, int tid) {
    if (tid < C) {
        float m = gsum_in[tid] / cnt;
        float var = gsq_in[tid] / cnt - m * m;
        float s = gam[tid] * rsqrtf(var + 1e-5f);
        ssc[tid] = s;
        ssh[tid] = bet[tid] - m * s;
    }
}

// ---------------- strided conv (k=4,s=2,p=1), smem-staged input tile (round-8 exact) ------
template<int CIN, int COUT, int HO, int WO, int PY, int PX, bool PRE>
__global__ void conv_s2_k(const float* __restrict__ in, const float* __restrict__ w,
                          const float* __restrict__ bias,
                          const float* __restrict__ gsum_in, const float* __restrict__ gsq_in,
                          const float* __restrict__ gam, const float* __restrict__ bet, float cnt,
                          float* __restrict__ out,
                          float* __restrict__ gsum, float* __restrict__ gsq) {
    constexpr int HI = HO * 2, WI = WO * 2;
    constexpr int TBX = 16, TBY = 8;
    constexpr int HT = TBY * PY, WT = TBX * PX;   // output tile per block
    constexpr int CX = WO / WT;
    constexpr int TROWS = 2 * HT + 2, TCOLS = 2 * WT + 2;
    constexpr int TCS = TCOLS + 1;
    constexpr int NPIX = PY * PX;
    static_assert(COUT % 4 == 0, "packed path");
    __shared__ float ws[CIN * 16 * COUT];   // [ic][ky*4+kx][oc]
    __shared__ float tile[TROWS * TCS];
    __shared__ float ssum[COUT], ssq[COUT];
    __shared__ float ssc[(PRE ? CIN : 1)], ssh[(PRE ? CIN : 1)];
    int tid = threadIdx.x;
    for (int i = tid; i < CIN * 16 * COUT; i += 128) {
        int oc = i % COUT; int r = i / COUT; int k = r & 15; int ic = r >> 4;
        ws[i] = w[(oc * CIN + ic) * 16 + k];
    }
    if (tid < COUT) { ssum[tid] = 0.f; ssq[tid] = 0.f; }
    if constexpr (PRE) bn_block<CIN>(gsum_in, gsq_in, gam, bet, cnt, ssc, ssh, tid);

    int b = blockIdx.y;
    int chX = blockIdx.x % CX, chY = blockIdx.x / CX;
    int gy0 = 2 * (chY * HT) - 1, gx0 = 2 * (chX * WT) - 1;
    int tx = tid % TBX, ty = tid / TBX;
    int OYl = ty * PY, OXl = tx * PX;
    int OY = chY * HT + OYl, OX = chX * WT + OXl;

    ull acc2[NPIX][COUT / 2];
    #pragma unroll
    for (int p = 0; p < NPIX; p++)
        #pragma unroll
        for (int j = 0; j < COUT / 2; j++) acc2[p][j] = 0ull;

    const float* inb = in + (size_t)b * CIN * HI * WI;
    #pragma unroll 1
    for (int ic = 0; ic < CIN; ic++) {
        const float* ip = inb + (size_t)ic * HI * WI;
        __syncthreads();   // previous-iter readers done; orders ws/ssc on iter 0
        float sc = 1.f, sh = 0.f;
        if constexpr (PRE) { sc = ssc[ic]; sh = ssh[ic]; }
        for (int idx = tid; idx < TROWS * TCOLS; idx += 128) {
            int r = idx / TCOLS, c = idx % TCOLS;
            int gy = gy0 + r, gx = gx0 + c;
            float v = 0.f;
            if ((unsigned)gy < (unsigned)HI && (unsigned)gx < (unsigned)WI) {
                v = ip[(size_t)gy * WI + gx];
                if constexpr (PRE) v = fmaxf(fmaf(v, sc, sh), 0.f);
            }
            tile[r * TCS + c] = v;
        }
        __syncthreads();
        #pragma unroll
        for (int ky = 0; ky < 4; ky++) {
            #pragma unroll
            for (int kx = 0; kx < 4; kx++) {
                const ulonglong2* w4 = (const ulonglong2*)&ws[(ic * 16 + ky * 4 + kx) * COUT];
                ull w2[COUT / 2];
                #pragma unroll
                for (int jj = 0; jj < COUT / 4; jj++) {
                    ulonglong2 ww = w4[jj];
                    w2[2 * jj] = ww.x; w2[2 * jj + 1] = ww.y;
                }
                #pragma unroll
                for (int dy = 0; dy < PY; dy++) {
                    #pragma unroll
                    for (int dx = 0; dx < PX; dx++) {
                        float v = tile[(2 * (OYl + dy) + ky) * TCS + 2 * (OXl + dx) + kx];
                        ull v2 = pk2(v, v);
                        int pi = dy * PX + dx;
                        #pragma unroll
                        for (int j = 0; j < COUT / 2; j++)
                            acc2[pi][j] = fma2(v2, w2[j], acc2[pi][j]);
                    }
                }
            }
        }
    }

    float acc[NPIX][COUT];
    #pragma unroll
    for (int p = 0; p < NPIX; p++)
        #pragma unroll
        for (int j = 0; j < COUT / 2; j++) upk2(acc2[p][j], acc[p][2*j], acc[p][2*j+1]);

    float* ob = out + ((size_t)b * COUT) * HO * WO;
    #pragma unroll
    for (int oc = 0; oc < COUT; oc++) {
        float bz = bias[oc];
        #pragma unroll
        for (int dy = 0; dy < PY; dy++) {
            #pragma unroll
            for (int dx = 0; dx < PX; dx++) {
                int pi = dy * PX + dx;
                float v = acc[pi][oc] + bz;
                acc[pi][oc] = v;
                ob[(size_t)oc * HO * WO + (size_t)(OY + dy) * WO + OX + dx] = v;
            }
        }
    }

    int lane = tid & 31;
    #pragma unroll
    for (int oc = 0; oc < COUT; oc++) {
        float s = 0.f, qs = 0.f;
        #pragma unroll
        for (int p = 0; p < NPIX; p++) { float v = acc[p][oc]; s += v; qs = fmaf(v, v, qs); }
        s = warp_red(s); qs = warp_red(qs);
        if (lane == 0) { atomicAdd(&ssum[oc], s); atomicAdd(&ssq[oc], qs); }
    }
    __syncthreads();
    if (tid < COUT) { atomicAdd(&gsum[tid], ssum[tid]); atomicAdd(&gsq[tid], ssq[tid]); }
}

// ---------------- transposed conv via parity decomposition (round-8 exact) ----------------
template<int CIN, int COUT, int HO, int WO, int PP, bool PRE>
__global__ void convT_k(const float* __restrict__ in, const float* __restrict__ w,
                        const float* __restrict__ bias,
                        const float* __restrict__ gsum_in, const float* __restrict__ gsq_in,
                        const float* __restrict__ gam, const float* __restrict__ bet, float cnt,
                        float* __restrict__ out,
                        float* __restrict__ gsum, float* __restrict__ gsq) {
    constexpr int HI = HO / 2, WI = WO / 2;
    constexpr int WW = WO / 2;
    constexpr int TBX = 16, TBY = 8;
    constexpr int CX = WW / (TBX * PP);
    constexpr int NPIX = PP * PP;
    constexpr int PS = PP + 1;
    __shared__ float ws[CIN * 16 * COUT];   // [ic][ky*4+kx][oc]
    __shared__ float ssum[COUT], ssq[COUT];
    __shared__ float ssc[(PRE ? CIN : 1)], ssh[(PRE ? CIN : 1)];
    int tid = threadIdx.x;
    for (int i = tid; i < CIN * 16 * COUT; i += 128) {
        int oc = i % COUT; int r = i / COUT; int k = r & 15; int ic = r >> 4;
        ws[i] = w[(ic * COUT + oc) * 16 + k];   // torch layout [in][out][kh][kw]
    }
    if (tid < COUT) { ssum[tid] = 0.f; ssq[tid] = 0.f; }
    if constexpr (PRE) bn_block<CIN>(gsum_in, gsq_in, gam, bet, cnt, ssc, ssh, tid);
    __syncthreads();

    int b = blockIdx.y;
    int cz = blockIdx.z; int cy = cz >> 1, cx = cz & 1;
    int chX = blockIdx.x % CX, chY = blockIdx.x / CX;
    int tx = tid % TBX, ty = tid / TBX;
    int Y0 = (chY * TBY + ty) * PP, X0 = (chX * TBX + tx) * PP;

    float accS[NPIX][(COUT % 4 == 0) ? 1 : COUT];
    ull acc2[NPIX][(COUT % 4 == 0) ? COUT / 2 : 1];
    if constexpr (COUT % 4 == 0) {
        #pragma unroll
        for (int p = 0; p < NPIX; p++)
            #pragma unroll
            for (int j = 0; j < COUT / 2; j++) acc2[p][j] = 0ull;
    } else {
        #pragma unroll
        for (int p = 0; p < NPIX; p++)
            #pragma unroll
            for (int oc = 0; oc < COUT; oc++) accS[p][oc] = 0.f;
    }

    const float* inb = in + (size_t)b * CIN * HI * WI;
    #pragma unroll 1
    for (int ic = 0; ic < CIN; ic++) {
        const float* ip = inb + (size_t)ic * HI * WI;
        float sc = 1.f, sh = 0.f;
        if constexpr (PRE) { sc = ssc[ic]; sh = ssh[ic]; }
        float p[PS][PS];
        #pragma unroll
        for (int r = 0; r < PS; r++) {
            int gy = Y0 + cy - 1 + r;
            bool yok = (unsigned)gy < (unsigned)HI;
            const float* rp = ip + (size_t)gy * WI;
            #pragma unroll
            for (int c = 0; c < PS; c++) {
                int gx = X0 + cx - 1 + c;
                float v = 0.f;
                if (yok && (unsigned)gx < (unsigned)WI) {
                    v = rp[gx];
                    if constexpr (PRE) v = fmaxf(fmaf(v, sc, sh), 0.f);
                }
                p[r][c] = v;
            }
        }
        #pragma unroll
        for (int t = 0; t < 2; t++) {
            #pragma unroll
            for (int s = 0; s < 2; s++) {
                int ky = (1 - cy) + 2 * t, kx = (1 - cx) + 2 * s;
                const float* wr = &ws[(ic * 16 + ky * 4 + kx) * COUT];
                if constexpr (COUT % 4 == 0) {
                    const ulonglong2* w4 = (const ulonglong2*)wr;
                    ull w2[COUT / 2];
                    #pragma unroll
                    for (int jj = 0; jj < COUT / 4; jj++) {
                        ulonglong2 ww = w4[jj];
                        w2[2 * jj] = ww.x; w2[2 * jj + 1] = ww.y;
                    }
                    #pragma unroll
                    for (int dy = 0; dy < PP; dy++) {
                        #pragma unroll
                        for (int dx = 0; dx < PP; dx++) {
                            float v = p[dy + 1 - t][dx + 1 - s];
                            ull v2 = pk2(v, v);
                            int pi = dy * PP + dx;
                            #pragma unroll
                            for (int j = 0; j < COUT / 2; j++)
                                acc2[pi][j] = fma2(v2, w2[j], acc2[pi][j]);
                        }
                    }
                } else {
                    float wv = wr[0];
                    #pragma unroll
                    for (int dy = 0; dy < PP; dy++)
                        #pragma unroll
                        for (int dx = 0; dx < PP; dx++)
                            accS[dy * PP + dx][0] = fmaf(p[dy + 1 - t][dx + 1 - s], wv,
                                                         accS[dy * PP + dx][0]);
                }
            }
        }
    }

    float acc[NPIX][COUT];
    if constexpr (COUT % 4 == 0) {
        #pragma unroll
        for (int p = 0; p < NPIX; p++)
            #pragma unroll
            for (int j = 0; j < COUT / 2; j++) upk2(acc2[p][j], acc[p][2*j], acc[p][2*j+1]);
    } else {
        #pragma unroll
        for (int p = 0; p < NPIX; p++)
            #pragma unroll
            for (int oc = 0; oc < COUT; oc++) acc[p][oc] = accS[p][oc];
    }

    float* ob = out + ((size_t)b * COUT) * HO * WO;
    #pragma unroll
    for (int oc = 0; oc < COUT; oc++) {
        float bz = bias[oc];
        #pragma unroll
        for (int dy = 0; dy < PP; dy++) {
            #pragma unroll
            for (int dx = 0; dx < PP; dx++) {
                int pi = dy * PP + dx;
                float v = acc[pi][oc] + bz;
                acc[pi][oc] = v;
                int oy = 2 * (Y0 + dy) + cy, ox = 2 * (X0 + dx) + cx;
                ob[(size_t)oc * HO * WO + (size_t)oy * WO + ox] = v;
            }
        }
    }

    int lane = tid & 31;
    #pragma unroll
    for (int oc = 0; oc < COUT; oc++) {
        float s = 0.f, qs = 0.f;
        #pragma unroll
        for (int p = 0; p < NPIX; p++) { float v = acc[p][oc]; s += v; qs = fmaf(v, v, qs); }
        s = warp_red(s); qs = warp_red(qs);
        if (lane == 0) { atomicAdd(&ssum[oc], s); atomicAdd(&ssq[oc], qs); }
    }
    __syncthreads();
    if (tid < COUT) { atomicAdd(&gsum[tid], ssum[tid]); atomicAdd(&gsq[tid], ssq[tid]); }
}

// ---------------- quantizer: 2 adjacent vectors per thread (round-8 exact) ----------------
__global__ void quant_k(const float* __restrict__ q_raw, const float* __restrict__ cb,
                        float* __restrict__ qout, float* __restrict__ idx_out,
                        const float* __restrict__ gsum_in, const float* __restrict__ gsq_in,
                        const float* __restrict__ gam, const float* __restrict__ bet) {
    __shared__ float cbs[128 * 32];
    __shared__ float cns[128];
    __shared__ float ssc[32], ssh[32];
    int tid = threadIdx.x;   // 128 threads
    bn_block<32>(gsum_in, gsq_in, gam, bet, 65536.f, ssc, ssh, tid);
    __syncthreads();

    int vec = (blockIdx.x * 128 + tid) * 2;   // this thread: vec, vec+1 (same image)
    int b = vec >> 10, hw = vec & 1023;       // hw even -> float2 aligned

    const float* base = q_raw + ((size_t)b * 32) * 1024 + hw;
    ull za[16], zb[16];   // za[j] = (zA[2j], zA[2j+1]) for vec; zb for vec+1
    #pragma unroll
    for (int j = 0; j < 16; j++) {
        float2 v0 = *(const float2*)(base + (size_t)(2*j)   * 1024);
        float2 v1 = *(const float2*)(base + (size_t)(2*j+1) * 1024);
        float a0 = fmaxf(fmaf(v0.x, ssc[2*j],   ssh[2*j]),   0.f);
        float b0 = fmaxf(fmaf(v0.y, ssc[2*j],   ssh[2*j]),   0.f);
        float a1 = fmaxf(fmaf(v1.x, ssc[2*j+1], ssh[2*j+1]), 0.f);
        float b1 = fmaxf(fmaf(v1.y, ssc[2*j+1], ssh[2*j+1]), 0.f);
        za[j] = pk2(a0, a1);
        zb[j] = pk2(b0, b1);
    }

    float bestA = 3.4e38f, bestB = 3.4e38f; int biA = 0, biB = 0;
    #pragma unroll 1
    for (int t = 0; t < 4; t++) {
        __syncthreads();
        const float4* src = (const float4*)(cb + (size_t)t * 128 * 32);
        float4* dst = (float4*)cbs;
        #pragma unroll
        for (int j = 0; j < 8; j++) dst[tid + 128 * j] = src[tid + 128 * j];
        cns[tid] = g_cnorm[t * 128 + tid];
        __syncthreads();
        #pragma unroll 1
        for (int k = 0; k < 128; k++) {
            const ulonglong2* cp = (const ulonglong2*)(cbs + k * 32);
            ull p0 = 0ull, p1 = 0ull, q0 = 0ull, q1 = 0ull;
            #pragma unroll
            for (int i = 0; i < 8; i++) {
                ulonglong2 c2 = cp[i];
                p0 = fma2(za[2*i],   c2.x, p0);
                p1 = fma2(za[2*i+1], c2.y, p1);
                q0 = fma2(zb[2*i],   c2.x, q0);
                q1 = fma2(zb[2*i+1], c2.y, q1);
            }
            float x0, x1, x2, x3, y0, y1, y2, y3;
            upk2(p0, x0, x1); upk2(p1, x2, x3);
            upk2(q0, y0, y1); upk2(q1, y2, y3);
            float cn = cns[k];
            float sA = cn - 2.f * ((x0 + x1) + (x2 + x3));
            float sB = cn - 2.f * ((y0 + y1) + (y2 + y3));
            if (sA < bestA) { bestA = sA; biA = t * 128 + k; }
            if (sB < bestB) { bestB = sB; biB = t * 128 + k; }
        }
    }

    idx_out[vec]     = (float)biA;
    idx_out[vec + 1] = (float)biB;
    float* qb = qout + ((size_t)b * 32) * 1024 + hw;
    const float4* ca = (const float4*)(cb + (size_t)biA * 32);
    const float4* cbp = (const float4*)(cb + (size_t)biB * 32);
    float sse = 0.f;
    #pragma unroll
    for (int j = 0; j < 8; j++) {
        float4 qa = __ldg(&ca[j]);
        float4 qv = __ldg(&cbp[j]);
        float a0, a1, a2, a3, b0, b1, b2, b3;
        upk2(za[2*j],   a0, a1);
        upk2(za[2*j+1], a2, a3);
        upk2(zb[2*j],   b0, b1);
        upk2(zb[2*j+1], b2, b3);
        *(float2*)(qb + (size_t)(4*j+0) * 1024) = make_float2(qa.x, qv.x);
        *(float2*)(qb + (size_t)(4*j+1) * 1024) = make_float2(qa.y, qv.y);
        *(float2*)(qb + (size_t)(4*j+2) * 1024) = make_float2(qa.z, qv.z);
        *(float2*)(qb + (size_t)(4*j+3) * 1024) = make_float2(qa.w, qv.w);
        float e;
        e = qa.x - a0; sse = fmaf(e, e, sse);
        e = qa.y - a1; sse = fmaf(e, e, sse);
        e = qa.z - a2; sse = fmaf(e, e, sse);
        e = qa.w - a3; sse = fmaf(e, e, sse);
        e = qv.x - b0; sse = fmaf(e, e, sse);
        e = qv.y - b1; sse = fmaf(e, e, sse);
        e = qv.z - b2; sse = fmaf(e, e, sse);
        e = qv.w - b3; sse = fmaf(e, e, sse);
    }
    sse = warp_red(sse);
    if ((tid & 31) == 0) atomicAdd(&g_loss[0], sse);
}

// ---------------- final: BN6-apply, 8 elems/thread via float4, recon SSE ----------------
// grid MUST be 4194304 / (256*8) = 2048 blocks.
__global__ void final_k(const float* __restrict__ x, float* __restrict__ dout,
                        const float* __restrict__ gsum_in, const float* __restrict__ gsq_in,
                        const float* __restrict__ gam, const float* __restrict__ bet) {
    __shared__ float wsum[8];
    __shared__ float sbn[2];
    if (threadIdx.x == 0) {
        float m = gsum_in[0] * (1.f / 4194304.f);
        float var = gsq_in[0] * (1.f / 4194304.f) - m * m;
        float s = gam[0] * rsqrtf(var + 1e-5f);
        sbn[0] = s; sbn[1] = bet[0] - m * s;
    }
    __syncthreads();
    float sc = sbn[0], sh = sbn[1];
    size_t i0 = ((size_t)blockIdx.x * 256 + threadIdx.x) * 8;
    float s = 0.f;
    #pragma unroll
    for (int h = 0; h < 2; h++) {
        float4 v = *(const float4*)(g_buf7 + i0 + 4 * h);
        float4 xv = *(const float4*)(x + i0 + 4 * h);
        float y0 = fmaf(v.x, sc, sh), y1 = fmaf(v.y, sc, sh);
        float y2 = fmaf(v.z, sc, sh), y3 = fmaf(v.w, sc, sh);
        *(float4*)(dout + i0 + 4 * h) = make_float4(y0, y1, y2, y3);
        float d0 = xv.x - y0, d1 = xv.y - y1, d2 = xv.z - y2, d3 = xv.w - y3;
        s = fmaf(d0, d0, fmaf(d1, d1, fmaf(d2, d2, fmaf(d3, d3, s))));
    }
    s = warp_red(s);
    if ((threadIdx.x & 31) == 0) wsum[threadIdx.x >> 5] = s;
    __syncthreads();
    if (threadIdx.x == 0) {
        float t = 0.f;
        #pragma unroll
        for (int j = 0; j < 8; j++) t += wsum[j];
        atomicAdd(&g_loss[1], t);
    }
}

__global__ void loss_k(float* __restrict__ dloss) {
    dloss[0] = 1.2f * g_loss[0] * (1.f / 2097152.f) + g_loss[1] * (1.f / 4194304.f);
}

// ---------------- launcher ----------------
extern "C" void kernel_launch(void* const* d_in, const int* in_sizes, int n_in,
                              void* d_out, int out_size) {
    const float* x      = (const float*)d_in[0];
    const float* enc_w1 = (const float*)d_in[1];
    const float* enc_b1 = (const float*)d_in[2];
    const float* enc_w2 = (const float*)d_in[3];
    const float* enc_b2 = (const float*)d_in[4];
    const float* enc_w3 = (const float*)d_in[5];
    const float* enc_b3 = (const float*)d_in[6];
    const float* enc_g1 = (const float*)d_in[7];
    const float* enc_be1= (const float*)d_in[8];
    const float* enc_g2 = (const float*)d_in[9];
    const float* enc_be2= (const float*)d_in[10];
    const float* enc_g3 = (const float*)d_in[11];
    const float* enc_be3= (const float*)d_in[12];
    const float* cb     = (const float*)d_in[13];
    const float* dec_w1 = (const float*)d_in[14];
    const float* dec_b1 = (const float*)d_in[15];
    const float* dec_w2 = (const float*)d_in[16];
    const float* dec_b2 = (const float*)d_in[17];
    const float* dec_w3 = (const float*)d_in[18];
    const float* dec_b3 = (const float*)d_in[19];
    const float* dec_g1 = (const float*)d_in[20];
    const float* dec_be1= (const float*)d_in[21];
    const float* dec_g2 = (const float*)d_in[22];
    const float* dec_be2= (const float*)d_in[23];
    const float* dec_g3 = (const float*)d_in[24];
    const float* dec_be3= (const float*)d_in[25];

    float* o = (float*)d_out;
    float* o_loss = o + 4194304;
    float* o_idx  = o + 4194305;

    static float *buf1,*buf2,*buf3,*buf4,*buf5,*buf6,*buf7,*sum,*sq;
    static bool init = false;
    if (!init) {
        cudaGetSymbolAddress((void**)&buf1, g_buf1);
        cudaGetSymbolAddress((void**)&buf2, g_buf2);
        cudaGetSymbolAddress((void**)&buf3, g_buf3);
        cudaGetSymbolAddress((void**)&buf4, g_buf4);
        cudaGetSymbolAddress((void**)&buf5, g_buf5);
        cudaGetSymbolAddress((void**)&buf6, g_buf6);
        cudaGetSymbolAddress((void**)&buf7, g_buf7);
        cudaGetSymbolAddress((void**)&sum,  g_sum);
        cudaGetSymbolAddress((void**)&sq,   g_sq);
        init = true;
    }

    init_k<<<2, 256>>>(cb);                                            // launch 1

    // encoder (round-8 exact)
    conv_s2_k<1,16,128,128,2,2,false><<<dim3(32, NB), 128>>>(          // launch 2
        x, enc_w1, enc_b1, nullptr, nullptr, nullptr, nullptr, 0.f,
        buf1, sum + 0, sq + 0);
    conv_s2_k<16,16,64,64,2,2,true><<<dim3(8, NB), 128>>>(             // launch 3
        buf1, enc_w2, enc_b2, sum + 0, sq + 0, enc_g1, enc_be1, 1048576.f,
        buf2, sum + 32, sq + 32);
    conv_s2_k<16,32,32,32,1,2,true><<<dim3(4, NB), 128>>>(             // launch 4
        buf2, enc_w3, enc_b3, sum + 32, sq + 32, enc_g2, enc_be2, 262144.f,
        buf3, sum + 64, sq + 64);

    // quantizer (round-8 exact)
    quant_k<<<256, 128>>>(buf3, cb, buf4, o_idx, sum + 64, sq + 64, enc_g3, enc_be3);  // launch 5

    // decoder (round-8 exact)
    convT_k<32,16,64,64,2,false><<<dim3(2, NB, 4), 128>>>(             // launch 6
        buf4, dec_w1, dec_b1, nullptr, nullptr, nullptr, nullptr, 0.f,
        buf5, sum + 96, sq + 96);
    convT_k<16,16,128,128,2,true><<<dim3(8, NB, 4), 128>>>(            // launch 7
        buf5, dec_w2, dec_b2, sum + 96, sq + 96, dec_g1, dec_be1, 262144.f,
        buf6, sum + 128, sq + 128);
    convT_k<16,1,256,256,4,true><<<dim3(8, NB, 4), 128>>>(             // launch 8
        buf6, dec_w3, dec_b3, sum + 128, sq + 128, dec_g2, dec_be2, 1048576.f,
        buf7, sum + 160, sq + 160);

    // output + losses  (2048 blocks x 256 thr x 8 elems = 4194304)
    final_k<<<2048, 256>>>(x, o, sum + 160, sq + 160, dec_g3, dec_be3);  // launch 9
    loss_k<<<1, 1>>>(o_loss);                                             // launch 10
}